// round 3
// baseline (speedup 1.0000x reference)
#include <cuda_runtime.h>
#include <math.h>

#define B_TOTAL 65536
#define FEAT    584

// ---------------- scratch (static device globals; no runtime allocation) ----
__device__ float g_feats[B_TOTAL * FEAT];   // 153 MB
__device__ float g_h1[B_TOTAL * 192];       // 50 MB  (cols 0-127 pt1, 128-191 cf1)

// ============================================================================
// Kernel 1: conv1->relu->conv2->relu->maxpool->conv3->relu + quantum -> feats
// warp-per-sample, 16 warps (=16 samples) per CTA.
// ============================================================================
#define K1_WARPS   16
#define K1_THREADS (K1_WARPS * 32)

// shared-memory float offsets (padded strides coprime with 32 banks)
#define OFF_W1   0          // 16 x 29   (27 used)
#define OFF_B1   464        // 16
#define OFF_W2   480        // 32 x 145  (144 used)
#define OFF_B2   5120       // 32
#define OFF_W3   5152       // 64 x 289  (288 used)
#define OFF_B3   23648      // 64
#define OFF_QP   23712      // 72
#define OFF_WARP 23784
#define WARP_STRIDE 1840    // board 112 | buf1 576 | buf2 1152
#define SMEM1_FLOATS (OFF_WARP + K1_WARPS * WARP_STRIDE)   // 53224 -> 212896 B

__global__ void __launch_bounds__(K1_THREADS, 1)
k1_conv(const float* __restrict__ board,
        const float* __restrict__ c1w, const float* __restrict__ c1b,
        const float* __restrict__ c2w, const float* __restrict__ c2b,
        const float* __restrict__ c3w, const float* __restrict__ c3b,
        const float* __restrict__ qp)
{
    extern __shared__ float sm[];
    const int tid = threadIdx.x;

    // ---- cooperative weight load (with bank-padding) ----
    for (int i = tid; i < 16 * 27; i += K1_THREADS) {
        int oc = i / 27, r = i - oc * 27;
        sm[OFF_W1 + oc * 29 + r] = c1w[i];
    }
    for (int i = tid; i < 16; i += K1_THREADS) sm[OFF_B1 + i] = c1b[i];
    for (int i = tid; i < 32 * 144; i += K1_THREADS) {
        int oc = i / 144, r = i - oc * 144;
        sm[OFF_W2 + oc * 145 + r] = c2w[i];
    }
    for (int i = tid; i < 32; i += K1_THREADS) sm[OFF_B2 + i] = c2b[i];
    for (int i = tid; i < 64 * 288; i += K1_THREADS) {
        int oc = i / 288, r = i - oc * 288;
        sm[OFF_W3 + oc * 289 + r] = c3w[i];
    }
    for (int i = tid; i < 64; i += K1_THREADS) sm[OFF_B3 + i] = c3b[i];
    for (int i = tid; i < 72; i += K1_THREADS) sm[OFF_QP + i] = qp[i];
    __syncthreads();

    const int warp = tid >> 5;
    const int lane = tid & 31;
    const int s    = blockIdx.x * K1_WARPS + warp;

    float* boardW = sm + OFF_WARP + warp * WARP_STRIDE;       // 108 used
    float* buf1W  = boardW + 112;                             // 576
    float* buf2W  = buf1W + 576;                              // 1152
    const float* w1s = sm + OFF_W1;
    const float* b1s = sm + OFF_B1;
    const float* w2s = sm + OFF_W2;
    const float* b2s = sm + OFF_B2;
    const float* w3s = sm + OFF_W3;
    const float* b3s = sm + OFF_B3;
    const float* qps = sm + OFF_QP;

    // ---- stage board (3,6,6) = 108 floats ----
    #pragma unroll
    for (int k = 0; k < 4; ++k) {
        int idx = lane + 32 * k;
        if (idx < 108) boardW[idx] = board[(long long)s * 108 + idx];
    }
    __syncwarp();

    // ---- conv1: (3,6,6)->(16,6,6), relu ----
    #pragma unroll 1
    for (int k = 0; k < 18; ++k) {
        int o   = lane + 32 * k;           // 0..575
        int oc  = o / 36;
        int pix = o - oc * 36;
        int y = pix / 6, x = pix - y * 6;
        float acc = b1s[oc];
        #pragma unroll
        for (int ic = 0; ic < 3; ++ic) {
            #pragma unroll
            for (int ky = 0; ky < 3; ++ky) {
                int iy = y + ky - 1;
                if ((unsigned)iy < 6u) {
                    #pragma unroll
                    for (int kx = 0; kx < 3; ++kx) {
                        int ix = x + kx - 1;
                        if ((unsigned)ix < 6u)
                            acc = fmaf(boardW[ic * 36 + iy * 6 + ix],
                                       w1s[oc * 29 + ic * 9 + ky * 3 + kx], acc);
                    }
                }
            }
        }
        buf1W[o] = fmaxf(acc, 0.f);
    }
    __syncwarp();

    // ---- conv2: (16,6,6)->(32,6,6), relu. lane = out-channel, acc over 36 px
    {
        float acc[36];
        #pragma unroll
        for (int p = 0; p < 36; ++p) acc[p] = b2s[lane];
        #pragma unroll 1
        for (int ic = 0; ic < 16; ++ic) {
            float in[36];
            const float4* s4 = reinterpret_cast<const float4*>(&buf1W[ic * 36]);
            #pragma unroll
            for (int j = 0; j < 9; ++j) {
                float4 v = s4[j];
                in[4 * j + 0] = v.x; in[4 * j + 1] = v.y;
                in[4 * j + 2] = v.z; in[4 * j + 3] = v.w;
            }
            float w[9];
            #pragma unroll
            for (int t = 0; t < 9; ++t) w[t] = w2s[lane * 145 + ic * 9 + t];
            #pragma unroll
            for (int p = 0; p < 36; ++p) {
                const int y = p / 6, x = p - (p / 6) * 6;
                #pragma unroll
                for (int t = 0; t < 9; ++t) {
                    const int iy = y + t / 3 - 1;
                    const int ix = x + t % 3 - 1;
                    if (iy >= 0 && iy < 6 && ix >= 0 && ix < 6)
                        acc[p] = fmaf(in[iy * 6 + ix], w[t], acc[p]);
                }
            }
        }
        #pragma unroll
        for (int p = 0; p < 36; ++p) buf2W[lane * 36 + p] = fmaxf(acc[p], 0.f);
    }
    __syncwarp();

    // ---- maxpool 2x2: (32,6,6)->(32,3,3) into buf1W (reuse) ----
    #pragma unroll
    for (int k = 0; k < 9; ++k) {
        int o = lane + 32 * k;             // 0..287
        int c = o / 9;
        int pp = o - c * 9;
        int py = pp / 3, px = pp - py * 3;
        const float* src = &buf2W[c * 36 + py * 12 + px * 2];
        buf1W[o] = fmaxf(fmaxf(src[0], src[1]), fmaxf(src[6], src[7]));
    }
    __syncwarp();

    // ---- conv3: (32,3,3)->(64,3,3), relu. lane owns oc=lane and lane+32 ----
    {
        float a0[9], a1[9];
        #pragma unroll
        for (int p = 0; p < 9; ++p) { a0[p] = b3s[lane]; a1[p] = b3s[lane + 32]; }
        #pragma unroll 1
        for (int ic = 0; ic < 32; ++ic) {
            float in[9];
            #pragma unroll
            for (int p = 0; p < 9; ++p) in[p] = buf1W[ic * 9 + p];
            float w0[9], w1v[9];
            #pragma unroll
            for (int t = 0; t < 9; ++t) {
                w0[t]  = w3s[lane * 289 + ic * 9 + t];
                w1v[t] = w3s[(lane + 32) * 289 + ic * 9 + t];
            }
            #pragma unroll
            for (int p = 0; p < 9; ++p) {
                const int y = p / 3, x = p - (p / 3) * 3;
                #pragma unroll
                for (int t = 0; t < 9; ++t) {
                    const int iy = y + t / 3 - 1;
                    const int ix = x + t % 3 - 1;
                    if (iy >= 0 && iy < 3 && ix >= 0 && ix < 3) {
                        float v = in[iy * 3 + ix];
                        a0[p] = fmaf(v, w0[t],  a0[p]);
                        a1[p] = fmaf(v, w1v[t], a1[p]);
                    }
                }
            }
        }
        #pragma unroll
        for (int p = 0; p < 9; ++p) {
            buf2W[lane * 9 + p]        = fmaxf(a0[p], 0.f);
            buf2W[(lane + 32) * 9 + p] = fmaxf(a1[p], 0.f);
        }
    }

    // ---- quantum sim: lanes 0..7, q_feat from board_flat[:, :8] ----
    if (lane < 8) {
        float x  = boardW[lane];
        float xn = boardW[(lane + 1) & 7];
        float qs = 0.f;
        #pragma unroll
        for (int l = 0; l < 3; ++l) {
            float r0 = qps[l * 24 + lane * 3 + 0];
            float r1 = qps[l * 24 + lane * 3 + 1];
            float r2 = qps[l * 24 + lane * 3 + 2];
            qs = sinf(r0 * x) * cosf(r1 * xn) + tanhf(r2 * qs);
        }
        buf2W[576 + lane] = qs;
    }
    __syncwarp();

    // ---- coalesced global write of 584 feats ----
    float* dst = g_feats + (long long)s * FEAT;
    #pragma unroll
    for (int k = 0; k < 19; ++k) {
        int idx = lane + 32 * k;
        if (idx < FEAT) dst[idx] = buf2W[idx];
    }
}

// ============================================================================
// Kernel 2: h1 = relu(feats @ [pt_w1 | cf_w1] + bias)   (65536x584 x 584x192)
// BM=128, BN=64, BK=8, 256 threads, 8x4 micro-tile per thread.
// ============================================================================
__global__ void __launch_bounds__(256)
k2_gemm(const float* __restrict__ ptw1, const float* __restrict__ ptb1,
        const float* __restrict__ cfw1, const float* __restrict__ cfb1)
{
    __shared__ float As[8][132];
    __shared__ float Ws[8][64];

    const int tid = threadIdx.x;
    const int tx = tid & 15;        // 0..15 -> 4 cols each
    const int ty = tid >> 4;        // 0..15 -> 8 rows each
    const int rowBase = blockIdx.x * 128;
    const int colBase = blockIdx.y * 64;   // 0,64 -> pt ; 128 -> cf

    float acc[8][4];
    #pragma unroll
    for (int j = 0; j < 8; ++j)
        #pragma unroll
        for (int i = 0; i < 4; ++i) acc[j][i] = 0.f;

    const int rA = tid >> 1;
    const int kpA = (tid & 1) * 4;
    const int kkW = tid >> 5;
    const int cW = (tid & 31) * 2;

    for (int k0 = 0; k0 < FEAT; k0 += 8) {
        // load A tile 128x8 (float4 per thread)
        float4 av = *reinterpret_cast<const float4*>(
            g_feats + (long long)(rowBase + rA) * FEAT + k0 + kpA);
        As[kpA + 0][rA] = av.x; As[kpA + 1][rA] = av.y;
        As[kpA + 2][rA] = av.z; As[kpA + 3][rA] = av.w;

        // load W tile 8x64 (float2 per thread)
        float2 wv;
        if (colBase < 128)
            wv = *reinterpret_cast<const float2*>(ptw1 + (k0 + kkW) * 128 + colBase + cW);
        else
            wv = *reinterpret_cast<const float2*>(cfw1 + (k0 + kkW) * 64 + cW);
        Ws[kkW][cW] = wv.x; Ws[kkW][cW + 1] = wv.y;
        __syncthreads();

        #pragma unroll
        for (int kk = 0; kk < 8; ++kk) {
            float a[8], w[4];
            #pragma unroll
            for (int j = 0; j < 8; ++j) a[j] = As[kk][ty * 8 + j];
            #pragma unroll
            for (int i = 0; i < 4; ++i) w[i] = Ws[kk][tx * 4 + i];
            #pragma unroll
            for (int j = 0; j < 8; ++j)
                #pragma unroll
                for (int i = 0; i < 4; ++i)
                    acc[j][i] = fmaf(a[j], w[i], acc[j][i]);
        }
        __syncthreads();
    }

    // epilogue: +bias, relu, store float4
    const int jg0 = colBase + tx * 4;
    float bias[4];
    #pragma unroll
    for (int i = 0; i < 4; ++i)
        bias[i] = (colBase < 128) ? ptb1[jg0 + i] : cfb1[jg0 + i - 128];

    #pragma unroll
    for (int j = 0; j < 8; ++j) {
        const long long row = rowBase + ty * 8 + j;
        float4 v;
        v.x = fmaxf(acc[j][0] + bias[0], 0.f);
        v.y = fmaxf(acc[j][1] + bias[1], 0.f);
        v.z = fmaxf(acc[j][2] + bias[2], 0.f);
        v.w = fmaxf(acc[j][3] + bias[3], 0.f);
        *reinterpret_cast<float4*>(g_h1 + row * 192 + jg0) = v;
    }
}

// ============================================================================
// Kernel 3: heads. warp-per-sample.
//   t2 = relu(t1 @ pt_w2 + b2); logits = t2 @ pt_w3 + b3; softmax
//   conf = sigmoid(c1 @ cf_w2 + cf_b2)
// ============================================================================
__global__ void __launch_bounds__(256)
k3_heads(const float* __restrict__ ptw2, const float* __restrict__ ptb2,
         const float* __restrict__ ptw3, const float* __restrict__ ptb3,
         const float* __restrict__ cfw2, const float* __restrict__ cfb2,
         float* __restrict__ out)
{
    __shared__ float w2s[128 * 64];
    __shared__ float b2s[64], w3s[128], b3s[2], cw2s[64];
    __shared__ float rowS[8][256];   // [0..191]=h1 row, [192..255]=t2

    const int tid = threadIdx.x;
    for (int i = tid; i < 128 * 64; i += 256) w2s[i] = ptw2[i];
    if (tid < 64)  b2s[tid]  = ptb2[tid];
    if (tid < 128) w3s[tid]  = ptw3[tid];
    if (tid < 2)   b3s[tid]  = ptb3[tid];
    if (tid < 64)  cw2s[tid] = cfw2[tid];
    const float cb2 = cfb2[0];
    __syncthreads();

    const int warp = tid >> 5, lane = tid & 31;
    const int s = blockIdx.x * 8 + warp;
    float* rw = rowS[warp];

    #pragma unroll
    for (int k = 0; k < 6; ++k) {
        int idx = lane + 32 * k;
        rw[idx] = g_h1[(long long)s * 192 + idx];
    }
    __syncwarp();

    // 128 -> 64 (two output cols per lane)
    const int j0 = lane, j1 = lane + 32;
    float t0 = b2s[j0], t1 = b2s[j1];
    #pragma unroll 4
    for (int k = 0; k < 128; ++k) {
        float f = rw[k];
        t0 = fmaf(f, w2s[k * 64 + j0], t0);
        t1 = fmaf(f, w2s[k * 64 + j1], t1);
    }
    rw[192 + j0] = fmaxf(t0, 0.f);
    rw[192 + j1] = fmaxf(t1, 0.f);
    __syncwarp();

    float res = 0.f;
    if (lane < 2) {                      // logits
        float lg = b3s[lane];
        #pragma unroll 4
        for (int k = 0; k < 64; ++k) lg = fmaf(rw[192 + k], w3s[k * 2 + lane], lg);
        res = lg;
    } else if (lane == 2) {              // confidence pre-activation
        float cf = cb2;
        #pragma unroll 4
        for (int k = 0; k < 64; ++k) cf = fmaf(rw[128 + k], cw2s[k], cf);
        res = cf;
    }
    const float l0 = __shfl_sync(0xffffffffu, res, 0);
    const float l1 = __shfl_sync(0xffffffffu, res, 1);
    const float cz = __shfl_sync(0xffffffffu, res, 2);

    if (lane == 0) {
        float m = fmaxf(l0, l1);
        float e0 = expf(l0 - m), e1 = expf(l1 - m);
        float inv = 1.f / (e0 + e1);
        out[(long long)s * 3 + 0] = e0 * inv;
        out[(long long)s * 3 + 1] = e1 * inv;
        out[(long long)s * 3 + 2] = 1.f / (1.f + expf(-cz));
    }
}

// ============================================================================
extern "C" void kernel_launch(void* const* d_in, const int* in_sizes, int n_in,
                              void* d_out, int out_size)
{
    const float* board = (const float*)d_in[0];
    // d_in[1] = target_positions (int64) — mathematically unused
    const float* c1w  = (const float*)d_in[2];
    const float* c1b  = (const float*)d_in[3];
    const float* c2w  = (const float*)d_in[4];
    const float* c2b  = (const float*)d_in[5];
    const float* c3w  = (const float*)d_in[6];
    const float* c3b  = (const float*)d_in[7];
    const float* qp   = (const float*)d_in[8];
    const float* ptw1 = (const float*)d_in[9];
    const float* ptb1 = (const float*)d_in[10];
    const float* ptw2 = (const float*)d_in[11];
    const float* ptb2 = (const float*)d_in[12];
    const float* ptw3 = (const float*)d_in[13];
    const float* ptb3 = (const float*)d_in[14];
    const float* cfw1 = (const float*)d_in[15];
    const float* cfb1 = (const float*)d_in[16];
    const float* cfw2 = (const float*)d_in[17];
    const float* cfb2 = (const float*)d_in[18];

    cudaFuncSetAttribute(k1_conv, cudaFuncAttributeMaxDynamicSharedMemorySize,
                         SMEM1_FLOATS * (int)sizeof(float));

    k1_conv<<<B_TOTAL / K1_WARPS, K1_THREADS, SMEM1_FLOATS * sizeof(float)>>>(
        board, c1w, c1b, c2w, c2b, c3w, c3b, qp);

    k2_gemm<<<dim3(B_TOTAL / 128, 3, 1), 256>>>(ptw1, ptb1, cfw1, cfb1);

    k3_heads<<<B_TOTAL / 8, 256>>>(ptw2, ptb2, ptw3, ptb3, cfw2, cfb2,
                                   (float*)d_out);
}

// round 5
// speedup vs baseline: 1.1765x; 1.1765x over previous
#include <cuda_runtime.h>
#include <math.h>

#define B_TOTAL 65536
#define FEAT    584

// ---------------- scratch (static device globals; no runtime allocation) ----
__device__ float g_feats[B_TOTAL * FEAT];   // 153 MB
__device__ float g_h1[B_TOTAL * 192];       // 50 MB  (cols 0-127 pt1, 128-191 cf1)

// ============================================================================
// Kernel 1: conv1->relu->conv2->relu->maxpool->conv3->relu + quantum -> feats
// warp-per-sample, 32 warps (=32 samples) per CTA, 1024 threads.
// ============================================================================
#define K1_WARPS   32
#define K1_THREADS (K1_WARPS * 32)

// shared-memory float offsets (padded strides coprime with 32 banks)
#define OFF_W1   0          // 16 x 29   (27 used)
#define OFF_B1   464        // 16
#define OFF_W2   480        // 32 x 145  (144 used)
#define OFF_B2   5120       // 32
#define OFF_W3   5152       // 64 x 289  (288 used)
#define OFF_B3   23648      // 64
#define OFF_QP   23712      // 72
#define OFF_WARP 23784
// per-warp: board 108 | buf1 576 | pooled 320 (32ch x stride10) -> 1004, pad 1008
#define WARP_STRIDE 1008
#define SMEM1_FLOATS (OFF_WARP + K1_WARPS * WARP_STRIDE)   // 56040 -> 224160 B

__global__ void __launch_bounds__(K1_THREADS, 1)
k1_conv(const float* __restrict__ board,
        const float* __restrict__ c1w, const float* __restrict__ c1b,
        const float* __restrict__ c2w, const float* __restrict__ c2b,
        const float* __restrict__ c3w, const float* __restrict__ c3b,
        const float* __restrict__ qp)
{
    extern __shared__ float sm[];
    const int tid = threadIdx.x;

    // ---- cooperative weight load (with bank-padding) ----
    for (int i = tid; i < 16 * 27; i += K1_THREADS) {
        int oc = i / 27, r = i - oc * 27;
        sm[OFF_W1 + oc * 29 + r] = c1w[i];
    }
    for (int i = tid; i < 16; i += K1_THREADS) sm[OFF_B1 + i] = c1b[i];
    for (int i = tid; i < 32 * 144; i += K1_THREADS) {
        int oc = i / 144, r = i - oc * 144;
        sm[OFF_W2 + oc * 145 + r] = c2w[i];
    }
    for (int i = tid; i < 32; i += K1_THREADS) sm[OFF_B2 + i] = c2b[i];
    for (int i = tid; i < 64 * 288; i += K1_THREADS) {
        int oc = i / 288, r = i - oc * 288;
        sm[OFF_W3 + oc * 289 + r] = c3w[i];
    }
    for (int i = tid; i < 64; i += K1_THREADS) sm[OFF_B3 + i] = c3b[i];
    for (int i = tid; i < 72; i += K1_THREADS) sm[OFF_QP + i] = qp[i];
    __syncthreads();

    const int warp = tid >> 5;
    const int lane = tid & 31;
    const int s    = blockIdx.x * K1_WARPS + warp;

    float* boardW  = sm + OFF_WARP + warp * WARP_STRIDE;   // 108
    float* buf1W   = boardW + 108;                         // 576
    float* pooledW = buf1W + 576;                          // 320 (ch*10+p)
    const float* w1s = sm + OFF_W1;
    const float* b1s = sm + OFF_B1;
    const float* w2s = sm + OFF_W2;
    const float* b2s = sm + OFF_B2;
    const float* w3s = sm + OFF_W3;
    const float* b3s = sm + OFF_B3;
    const float* qps = sm + OFF_QP;

    // ---- stage board (3,6,6) = 108 floats (s*108 words = s*432B: 16B-aligned)
    if (lane < 27) {
        float4 v = reinterpret_cast<const float4*>(board + (long long)s * 108)[lane];
        reinterpret_cast<float4*>(boardW)[lane] = v;
    }
    __syncwarp();

    // ---- quantum sim early (board region is never overwritten, but keep in regs)
    float qfeat = 0.f;
    if (lane < 8) {
        float x  = boardW[lane];
        float xn = boardW[(lane + 1) & 7];
        float qs = 0.f;
        #pragma unroll
        for (int l = 0; l < 3; ++l) {
            float r0 = qps[l * 24 + lane * 3 + 0];
            float r1 = qps[l * 24 + lane * 3 + 1];
            float r2 = qps[l * 24 + lane * 3 + 2];
            qs = sinf(r0 * x) * cosf(r1 * xn) + tanhf(r2 * qs);
        }
        qfeat = qs;
    }

    // ---- conv1: (3,6,6)->(16,6,6), relu. lane=(oc in 0..15, pixel-half) ----
    {
        const int oc    = lane & 15;
        const int half  = lane >> 4;           // 0: out rows 0-2, 1: rows 3-5
        const int ibase = half ? 2 : 0;        // staged input rows ibase..ibase+3
        float acc[18];
        #pragma unroll
        for (int p = 0; p < 18; ++p) acc[p] = b1s[oc];

        #pragma unroll
        for (int ic = 0; ic < 3; ++ic) {
            float in[24];                       // 4 input rows
            #pragma unroll
            for (int j = 0; j < 6; ++j) {
                float4 v = reinterpret_cast<const float4*>(boardW)[ic * 9 + half * 3 + j];
                in[4 * j + 0] = v.x; in[4 * j + 1] = v.y;
                in[4 * j + 2] = v.z; in[4 * j + 3] = v.w;
            }
            float w[9];
            #pragma unroll
            for (int t = 0; t < 9; ++t) w[t] = w1s[oc * 29 + ic * 9 + t];

            #pragma unroll
            for (int p = 0; p < 18; ++p) {
                const int y = half * 3 + p / 6;
                const int x = p % 6;
                #pragma unroll
                for (int ky = 0; ky < 3; ++ky) {
                    const int iy = y + ky - 1;
                    if (iy >= 0 && iy < 6) {
                        const int liy = iy - ibase;
                        #pragma unroll
                        for (int kx = 0; kx < 3; ++kx) {
                            const int ix = x + kx - 1;
                            if (ix >= 0 && ix < 6)
                                acc[p] = fmaf(in[liy * 6 + ix], w[ky * 3 + kx], acc[p]);
                        }
                    }
                }
            }
        }
        // store relu'd as float2 pairs (offset oc*36+half*18 is even)
        float2* dst2 = reinterpret_cast<float2*>(buf1W + oc * 36 + half * 18);
        #pragma unroll
        for (int j = 0; j < 9; ++j)
            dst2[j] = make_float2(fmaxf(acc[2 * j], 0.f), fmaxf(acc[2 * j + 1], 0.f));
    }
    __syncwarp();

    // ---- conv2 (lane = oc) in 3 row-pair groups; pool+relu in registers ----
    {
        // group g: out rows 2g..2g+1; staged float4 window [f0, f0+nf)
        const int F0[3] = {0, 1, 4};
        const int NF[3] = {5, 7, 5};
        #pragma unroll
        for (int g = 0; g < 3; ++g) {
            const int f0 = F0[g], nf = NF[g];
            const int wb = f0 * 4;             // word offset of in[0]
            float acc[12];
            #pragma unroll
            for (int p = 0; p < 12; ++p) acc[p] = b2s[lane];

            #pragma unroll 1
            for (int ic = 0; ic < 16; ++ic) {
                float in[28];
                #pragma unroll
                for (int j = 0; j < 7; ++j) {
                    if (j < nf) {
                        float4 v = reinterpret_cast<const float4*>(buf1W)[ic * 9 + f0 + j];
                        in[4 * j + 0] = v.x; in[4 * j + 1] = v.y;
                        in[4 * j + 2] = v.z; in[4 * j + 3] = v.w;
                    }
                }
                float w[9];
                #pragma unroll
                for (int t = 0; t < 9; ++t) w[t] = w2s[lane * 145 + ic * 9 + t];

                #pragma unroll
                for (int p = 0; p < 12; ++p) {
                    const int y = 2 * g + p / 6;
                    const int x = p % 6;
                    #pragma unroll
                    for (int ky = 0; ky < 3; ++ky) {
                        const int iy = y + ky - 1;
                        if (iy >= 0 && iy < 6) {
                            #pragma unroll
                            for (int kx = 0; kx < 3; ++kx) {
                                const int ix = x + kx - 1;
                                if (ix >= 0 && ix < 6)
                                    acc[p] = fmaf(in[iy * 6 + ix - wb], w[ky * 3 + kx], acc[p]);
                            }
                        }
                    }
                }
            }
            // 2x2 maxpool of the two rows + relu -> pooled row g
            #pragma unroll
            for (int px = 0; px < 3; ++px) {
                float v = fmaxf(fmaxf(acc[2 * px], acc[2 * px + 1]),
                                fmaxf(acc[6 + 2 * px], acc[6 + 2 * px + 1]));
                pooledW[lane * 10 + g * 3 + px] = fmaxf(v, 0.f);
            }
        }
    }
    __syncwarp();

    // ---- conv3: (32,3,3)->(64,3,3), relu; write straight to g_feats ----
    float* dst = g_feats + (long long)s * FEAT;
    {
        float a0[9], a1[9];
        #pragma unroll
        for (int p = 0; p < 9; ++p) { a0[p] = b3s[lane]; a1[p] = b3s[lane + 32]; }

        #pragma unroll 1
        for (int ic = 0; ic < 32; ++ic) {
            float in[10];
            #pragma unroll
            for (int j = 0; j < 5; ++j) {      // broadcast float2 loads
                float2 v = reinterpret_cast<const float2*>(pooledW)[ic * 5 + j];
                in[2 * j] = v.x; in[2 * j + 1] = v.y;
            }
            float w0[9], w1v[9];
            #pragma unroll
            for (int t = 0; t < 9; ++t) {
                w0[t]  = w3s[lane * 289 + ic * 9 + t];
                w1v[t] = w3s[(lane + 32) * 289 + ic * 9 + t];
            }
            #pragma unroll
            for (int p = 0; p < 9; ++p) {
                const int y = p / 3, x = p - (p / 3) * 3;
                #pragma unroll
                for (int ky = 0; ky < 3; ++ky) {
                    const int iy = y + ky - 1;
                    if (iy >= 0 && iy < 3) {
                        #pragma unroll
                        for (int kx = 0; kx < 3; ++kx) {
                            const int ix = x + kx - 1;
                            if (ix >= 0 && ix < 3) {
                                float v = in[iy * 3 + ix];
                                a0[p] = fmaf(v, w0[ky * 3 + kx],  a0[p]);
                                a1[p] = fmaf(v, w1v[ky * 3 + kx], a1[p]);
                            }
                        }
                    }
                }
            }
        }
        #pragma unroll
        for (int p = 0; p < 9; ++p) {
            dst[lane * 9 + p]        = fmaxf(a0[p], 0.f);
            dst[(lane + 32) * 9 + p] = fmaxf(a1[p], 0.f);
        }
    }

    if (lane < 8) dst[576 + lane] = qfeat;
}

// ============================================================================
// Kernel 2: h1 = relu(feats @ [pt_w1 | cf_w1] + bias)   (65536x584 x 584x192)
// BM=128, BN=64, BK=8, 256 threads, 8x4 micro-tile per thread.
// ============================================================================
__global__ void __launch_bounds__(256)
k2_gemm(const float* __restrict__ ptw1, const float* __restrict__ ptb1,
        const float* __restrict__ cfw1, const float* __restrict__ cfb1)
{
    __shared__ float As[8][132];
    __shared__ float Ws[8][64];

    const int tid = threadIdx.x;
    const int tx = tid & 15;        // 0..15 -> 4 cols each
    const int ty = tid >> 4;        // 0..15 -> 8 rows each
    const int rowBase = blockIdx.x * 128;
    const int colBase = blockIdx.y * 64;   // 0,64 -> pt ; 128 -> cf

    float acc[8][4];
    #pragma unroll
    for (int j = 0; j < 8; ++j)
        #pragma unroll
        for (int i = 0; i < 4; ++i) acc[j][i] = 0.f;

    const int rA = tid >> 1;
    const int kpA = (tid & 1) * 4;
    const int kkW = tid >> 5;
    const int cW = (tid & 31) * 2;

    for (int k0 = 0; k0 < FEAT; k0 += 8) {
        // load A tile 128x8 (float4 per thread)
        float4 av = *reinterpret_cast<const float4*>(
            g_feats + (long long)(rowBase + rA) * FEAT + k0 + kpA);
        As[kpA + 0][rA] = av.x; As[kpA + 1][rA] = av.y;
        As[kpA + 2][rA] = av.z; As[kpA + 3][rA] = av.w;

        // load W tile 8x64 (float2 per thread)
        float2 wv;
        if (colBase < 128)
            wv = *reinterpret_cast<const float2*>(ptw1 + (k0 + kkW) * 128 + colBase + cW);
        else
            wv = *reinterpret_cast<const float2*>(cfw1 + (k0 + kkW) * 64 + cW);
        Ws[kkW][cW] = wv.x; Ws[kkW][cW + 1] = wv.y;
        __syncthreads();

        #pragma unroll
        for (int kk = 0; kk < 8; ++kk) {
            float a[8], w[4];
            #pragma unroll
            for (int j = 0; j < 8; ++j) a[j] = As[kk][ty * 8 + j];
            #pragma unroll
            for (int i = 0; i < 4; ++i) w[i] = Ws[kk][tx * 4 + i];
            #pragma unroll
            for (int j = 0; j < 8; ++j)
                #pragma unroll
                for (int i = 0; i < 4; ++i)
                    acc[j][i] = fmaf(a[j], w[i], acc[j][i]);
        }
        __syncthreads();
    }

    // epilogue: +bias, relu, store float4
    const int jg0 = colBase + tx * 4;
    float bias[4];
    #pragma unroll
    for (int i = 0; i < 4; ++i)
        bias[i] = (colBase < 128) ? ptb1[jg0 + i] : cfb1[jg0 + i - 128];

    #pragma unroll
    for (int j = 0; j < 8; ++j) {
        const long long row = rowBase + ty * 8 + j;
        float4 v;
        v.x = fmaxf(acc[j][0] + bias[0], 0.f);
        v.y = fmaxf(acc[j][1] + bias[1], 0.f);
        v.z = fmaxf(acc[j][2] + bias[2], 0.f);
        v.w = fmaxf(acc[j][3] + bias[3], 0.f);
        *reinterpret_cast<float4*>(g_h1 + row * 192 + jg0) = v;
    }
}

// ============================================================================
// Kernel 3: heads. warp-per-sample.
// ============================================================================
__global__ void __launch_bounds__(256)
k3_heads(const float* __restrict__ ptw2, const float* __restrict__ ptb2,
         const float* __restrict__ ptw3, const float* __restrict__ ptb3,
         const float* __restrict__ cfw2, const float* __restrict__ cfb2,
         float* __restrict__ out)
{
    __shared__ float w2s[128 * 64];
    __shared__ float b2s[64], w3s[128], b3s[2], cw2s[64];
    __shared__ float rowS[8][256];   // [0..191]=h1 row, [192..255]=t2

    const int tid = threadIdx.x;
    for (int i = tid; i < 128 * 64; i += 256) w2s[i] = ptw2[i];
    if (tid < 64)  b2s[tid]  = ptb2[tid];
    if (tid < 128) w3s[tid]  = ptw3[tid];
    if (tid < 2)   b3s[tid]  = ptb3[tid];
    if (tid < 64)  cw2s[tid] = cfw2[tid];
    const float cb2 = cfb2[0];
    __syncthreads();

    const int warp = tid >> 5, lane = tid & 31;
    const int s = blockIdx.x * 8 + warp;
    float* rw = rowS[warp];

    #pragma unroll
    for (int k = 0; k < 6; ++k) {
        int idx = lane + 32 * k;
        rw[idx] = g_h1[(long long)s * 192 + idx];
    }
    __syncwarp();

    // 128 -> 64 (two output cols per lane)
    const int j0 = lane, j1 = lane + 32;
    float t0 = b2s[j0], t1 = b2s[j1];
    #pragma unroll 4
    for (int k = 0; k < 128; ++k) {
        float f = rw[k];
        t0 = fmaf(f, w2s[k * 64 + j0], t0);
        t1 = fmaf(f, w2s[k * 64 + j1], t1);
    }
    rw[192 + j0] = fmaxf(t0, 0.f);
    rw[192 + j1] = fmaxf(t1, 0.f);
    __syncwarp();

    float res = 0.f;
    if (lane < 2) {                      // logits
        float lg = b3s[lane];
        #pragma unroll 4
        for (int k = 0; k < 64; ++k) lg = fmaf(rw[192 + k], w3s[k * 2 + lane], lg);
        res = lg;
    } else if (lane == 2) {              // confidence pre-activation
        float cf = cb2;
        #pragma unroll 4
        for (int k = 0; k < 64; ++k) cf = fmaf(rw[128 + k], cw2s[k], cf);
        res = cf;
    }
    const float l0 = __shfl_sync(0xffffffffu, res, 0);
    const float l1 = __shfl_sync(0xffffffffu, res, 1);
    const float cz = __shfl_sync(0xffffffffu, res, 2);

    if (lane == 0) {
        float m = fmaxf(l0, l1);
        float e0 = expf(l0 - m), e1 = expf(l1 - m);
        float inv = 1.f / (e0 + e1);
        out[(long long)s * 3 + 0] = e0 * inv;
        out[(long long)s * 3 + 1] = e1 * inv;
        out[(long long)s * 3 + 2] = 1.f / (1.f + expf(-cz));
    }
}

// ============================================================================
extern "C" void kernel_launch(void* const* d_in, const int* in_sizes, int n_in,
                              void* d_out, int out_size)
{
    const float* board = (const float*)d_in[0];
    // d_in[1] = target_positions (int64) — mathematically unused
    const float* c1w  = (const float*)d_in[2];
    const float* c1b  = (const float*)d_in[3];
    const float* c2w  = (const float*)d_in[4];
    const float* c2b  = (const float*)d_in[5];
    const float* c3w  = (const float*)d_in[6];
    const float* c3b  = (const float*)d_in[7];
    const float* qp   = (const float*)d_in[8];
    const float* ptw1 = (const float*)d_in[9];
    const float* ptb1 = (const float*)d_in[10];
    const float* ptw2 = (const float*)d_in[11];
    const float* ptb2 = (const float*)d_in[12];
    const float* ptw3 = (const float*)d_in[13];
    const float* ptb3 = (const float*)d_in[14];
    const float* cfw1 = (const float*)d_in[15];
    const float* cfb1 = (const float*)d_in[16];
    const float* cfw2 = (const float*)d_in[17];
    const float* cfb2 = (const float*)d_in[18];

    cudaFuncSetAttribute(k1_conv, cudaFuncAttributeMaxDynamicSharedMemorySize,
                         SMEM1_FLOATS * (int)sizeof(float));

    k1_conv<<<B_TOTAL / K1_WARPS, K1_THREADS, SMEM1_FLOATS * sizeof(float)>>>(
        board, c1w, c1b, c2w, c2b, c3w, c3b, qp);

    k2_gemm<<<dim3(B_TOTAL / 128, 3, 1), 256>>>(ptw1, ptb1, cfw1, cfb1);

    k3_heads<<<B_TOTAL / 8, 256>>>(ptw2, ptb2, ptw3, ptb3, cfw2, cfb2,
                                   (float*)d_out);
}

// round 6
// speedup vs baseline: 1.2904x; 1.0968x over previous
#include <cuda_runtime.h>
#include <math.h>

#define B_TOTAL 65536
#define FEAT    584
#define KPAD    640          // 584 padded to 10 chunks of 64 (zero-filled)

// ---------------- scratch (static device globals; no runtime allocation) ----
__device__ float g_feats[B_TOTAL * KPAD];   // 167 MB (stride 640, cols 584.. zero)
__device__ float g_h1[B_TOTAL * 192];       // 50 MB  (cols 0-127 pt1, 128-191 cf1)

// ============================================================================
// Kernel 1: conv1->relu->conv2->relu->maxpool->conv3->relu + quantum -> feats
// warp-per-sample, 32 warps (=32 samples) per CTA, 1024 threads.
// ============================================================================
#define K1_WARPS   32
#define K1_THREADS (K1_WARPS * 32)

#define OFF_W1   0          // 16 x 29   (27 used)
#define OFF_B1   464        // 16
#define OFF_W2   480        // 32 x 145  (144 used)
#define OFF_B2   5120       // 32
#define OFF_W3   5152       // 64 x 289  (288 used)
#define OFF_B3   23648      // 64
#define OFF_QP   23712      // 72
#define OFF_WARP 23784
#define WARP_STRIDE 1008
#define SMEM1_FLOATS (OFF_WARP + K1_WARPS * WARP_STRIDE)   // 56040 -> 224160 B

__global__ void __launch_bounds__(K1_THREADS, 1)
k1_conv(const float* __restrict__ board,
        const float* __restrict__ c1w, const float* __restrict__ c1b,
        const float* __restrict__ c2w, const float* __restrict__ c2b,
        const float* __restrict__ c3w, const float* __restrict__ c3b,
        const float* __restrict__ qp)
{
    extern __shared__ float sm[];
    const int tid = threadIdx.x;

    for (int i = tid; i < 16 * 27; i += K1_THREADS) {
        int oc = i / 27, r = i - oc * 27;
        sm[OFF_W1 + oc * 29 + r] = c1w[i];
    }
    for (int i = tid; i < 16; i += K1_THREADS) sm[OFF_B1 + i] = c1b[i];
    for (int i = tid; i < 32 * 144; i += K1_THREADS) {
        int oc = i / 144, r = i - oc * 144;
        sm[OFF_W2 + oc * 145 + r] = c2w[i];
    }
    for (int i = tid; i < 32; i += K1_THREADS) sm[OFF_B2 + i] = c2b[i];
    for (int i = tid; i < 64 * 288; i += K1_THREADS) {
        int oc = i / 288, r = i - oc * 288;
        sm[OFF_W3 + oc * 289 + r] = c3w[i];
    }
    for (int i = tid; i < 64; i += K1_THREADS) sm[OFF_B3 + i] = c3b[i];
    for (int i = tid; i < 72; i += K1_THREADS) sm[OFF_QP + i] = qp[i];
    __syncthreads();

    const int warp = tid >> 5;
    const int lane = tid & 31;
    const int s    = blockIdx.x * K1_WARPS + warp;

    float* boardW  = sm + OFF_WARP + warp * WARP_STRIDE;   // 108
    float* buf1W   = boardW + 108;                         // 576
    float* pooledW = buf1W + 576;                          // 320 (ch*10+p)
    const float* w1s = sm + OFF_W1;
    const float* b1s = sm + OFF_B1;
    const float* w2s = sm + OFF_W2;
    const float* b2s = sm + OFF_B2;
    const float* w3s = sm + OFF_W3;
    const float* b3s = sm + OFF_B3;
    const float* qps = sm + OFF_QP;

    // ---- stage board (3,6,6) = 108 floats ----
    if (lane < 27) {
        float4 v = reinterpret_cast<const float4*>(board + (long long)s * 108)[lane];
        reinterpret_cast<float4*>(boardW)[lane] = v;
    }
    __syncwarp();

    // ---- quantum sim early ----
    float qfeat = 0.f;
    if (lane < 8) {
        float x  = boardW[lane];
        float xn = boardW[(lane + 1) & 7];
        float qs = 0.f;
        #pragma unroll
        for (int l = 0; l < 3; ++l) {
            float r0 = qps[l * 24 + lane * 3 + 0];
            float r1 = qps[l * 24 + lane * 3 + 1];
            float r2 = qps[l * 24 + lane * 3 + 2];
            qs = sinf(r0 * x) * cosf(r1 * xn) + tanhf(r2 * qs);
        }
        qfeat = qs;
    }

    // ---- conv1: (3,6,6)->(16,6,6), relu. lane=(oc 0..15, pixel-half) ----
    {
        const int oc    = lane & 15;
        const int half  = lane >> 4;
        const int ibase = half ? 2 : 0;
        float acc[18];
        #pragma unroll
        for (int p = 0; p < 18; ++p) acc[p] = b1s[oc];

        #pragma unroll
        for (int ic = 0; ic < 3; ++ic) {
            float in[24];
            #pragma unroll
            for (int j = 0; j < 6; ++j) {
                float4 v = reinterpret_cast<const float4*>(boardW)[ic * 9 + half * 3 + j];
                in[4 * j + 0] = v.x; in[4 * j + 1] = v.y;
                in[4 * j + 2] = v.z; in[4 * j + 3] = v.w;
            }
            float w[9];
            #pragma unroll
            for (int t = 0; t < 9; ++t) w[t] = w1s[oc * 29 + ic * 9 + t];

            #pragma unroll
            for (int p = 0; p < 18; ++p) {
                const int y = half * 3 + p / 6;
                const int x = p % 6;
                #pragma unroll
                for (int ky = 0; ky < 3; ++ky) {
                    const int iy = y + ky - 1;
                    if (iy >= 0 && iy < 6) {
                        const int liy = iy - ibase;
                        #pragma unroll
                        for (int kx = 0; kx < 3; ++kx) {
                            const int ix = x + kx - 1;
                            if (ix >= 0 && ix < 6)
                                acc[p] = fmaf(in[liy * 6 + ix], w[ky * 3 + kx], acc[p]);
                        }
                    }
                }
            }
        }
        float2* dst2 = reinterpret_cast<float2*>(buf1W + oc * 36 + half * 18);
        #pragma unroll
        for (int j = 0; j < 9; ++j)
            dst2[j] = make_float2(fmaxf(acc[2 * j], 0.f), fmaxf(acc[2 * j + 1], 0.f));
    }
    __syncwarp();

    // ---- conv2 (lane = oc) in 3 row-pair groups; pool+relu in registers ----
    {
        const int F0[3] = {0, 1, 4};
        const int NF[3] = {5, 7, 5};
        #pragma unroll
        for (int g = 0; g < 3; ++g) {
            const int f0 = F0[g], nf = NF[g];
            const int wb = f0 * 4;
            float acc[12];
            #pragma unroll
            for (int p = 0; p < 12; ++p) acc[p] = b2s[lane];

            #pragma unroll 1
            for (int ic = 0; ic < 16; ++ic) {
                float in[28];
                #pragma unroll
                for (int j = 0; j < 7; ++j) {
                    if (j < nf) {
                        float4 v = reinterpret_cast<const float4*>(buf1W)[ic * 9 + f0 + j];
                        in[4 * j + 0] = v.x; in[4 * j + 1] = v.y;
                        in[4 * j + 2] = v.z; in[4 * j + 3] = v.w;
                    }
                }
                float w[9];
                #pragma unroll
                for (int t = 0; t < 9; ++t) w[t] = w2s[lane * 145 + ic * 9 + t];

                #pragma unroll
                for (int p = 0; p < 12; ++p) {
                    const int y = 2 * g + p / 6;
                    const int x = p % 6;
                    #pragma unroll
                    for (int ky = 0; ky < 3; ++ky) {
                        const int iy = y + ky - 1;
                        if (iy >= 0 && iy < 6) {
                            #pragma unroll
                            for (int kx = 0; kx < 3; ++kx) {
                                const int ix = x + kx - 1;
                                if (ix >= 0 && ix < 6)
                                    acc[p] = fmaf(in[iy * 6 + ix - wb], w[ky * 3 + kx], acc[p]);
                            }
                        }
                    }
                }
            }
            #pragma unroll
            for (int px = 0; px < 3; ++px) {
                float v = fmaxf(fmaxf(acc[2 * px], acc[2 * px + 1]),
                                fmaxf(acc[6 + 2 * px], acc[6 + 2 * px + 1]));
                pooledW[lane * 10 + g * 3 + px] = fmaxf(v, 0.f);
            }
        }
    }
    __syncwarp();

    // ---- conv3: (32,3,3)->(64,3,3), relu; write straight to g_feats ----
    float* dst = g_feats + (long long)s * KPAD;
    {
        float a0[9], a1[9];
        #pragma unroll
        for (int p = 0; p < 9; ++p) { a0[p] = b3s[lane]; a1[p] = b3s[lane + 32]; }

        #pragma unroll 1
        for (int ic = 0; ic < 32; ++ic) {
            float in[10];
            #pragma unroll
            for (int j = 0; j < 5; ++j) {
                float2 v = reinterpret_cast<const float2*>(pooledW)[ic * 5 + j];
                in[2 * j] = v.x; in[2 * j + 1] = v.y;
            }
            float w0[9], w1v[9];
            #pragma unroll
            for (int t = 0; t < 9; ++t) {
                w0[t]  = w3s[lane * 289 + ic * 9 + t];
                w1v[t] = w3s[(lane + 32) * 289 + ic * 9 + t];
            }
            #pragma unroll
            for (int p = 0; p < 9; ++p) {
                const int y = p / 3, x = p - (p / 3) * 3;
                #pragma unroll
                for (int ky = 0; ky < 3; ++ky) {
                    const int iy = y + ky - 1;
                    if (iy >= 0 && iy < 3) {
                        #pragma unroll
                        for (int kx = 0; kx < 3; ++kx) {
                            const int ix = x + kx - 1;
                            if (ix >= 0 && ix < 3) {
                                float v = in[iy * 3 + ix];
                                a0[p] = fmaf(v, w0[ky * 3 + kx],  a0[p]);
                                a1[p] = fmaf(v, w1v[ky * 3 + kx], a1[p]);
                            }
                        }
                    }
                }
            }
        }
        #pragma unroll
        for (int p = 0; p < 9; ++p) {
            dst[lane * 9 + p]        = fmaxf(a0[p], 0.f);
            dst[(lane + 32) * 9 + p] = fmaxf(a1[p], 0.f);
        }
    }

    if (lane < 8) dst[576 + lane] = qfeat;
    // zero-fill pad region [584, 640)
    for (int idx = 584 + lane; idx < KPAD; idx += 32) dst[idx] = 0.f;
}

// ============================================================================
// Kernel 2 (tf32 tensor-core): h1 = relu(feats @ [pt_w1|cf_w1] + bias)
// M=65536, N=192, K=640 (zero-padded). CTA tile 128x192, 256 thr, 8 warps
// (4m x 2n), warp tile 32x96 via mma.sync.m16n8k8.tf32. fp32 accumulate.
// ============================================================================
#define AS_STRIDE 68     // 64 + pad (bank-safe for a-frag pattern)
#define BS_STRIDE 200    // 192 + pad (bank-safe for b-frag pattern)
#define SMEM2_FLOATS (128 * AS_STRIDE + 64 * BS_STRIDE + 192)  // 21696 -> 86784 B

__device__ __forceinline__ unsigned f2tf32(float f) {
    unsigned u;
    asm("cvt.rna.tf32.f32 %0, %1;" : "=r"(u) : "f"(f));
    return u;
}

__global__ void __launch_bounds__(256, 1)
k2_gemm_tc(const float* __restrict__ ptw1, const float* __restrict__ ptb1,
           const float* __restrict__ cfw1, const float* __restrict__ cfb1)
{
    extern __shared__ float sm2[];
    unsigned* As = reinterpret_cast<unsigned*>(sm2);                  // [128][68]
    unsigned* Bs = reinterpret_cast<unsigned*>(sm2 + 128 * AS_STRIDE);// [64][200]
    float*    biasS = sm2 + 128 * AS_STRIDE + 64 * BS_STRIDE;         // [192]

    const int tid  = threadIdx.x;
    const int lane = tid & 31;
    const int warp = tid >> 5;
    const int warpM = (warp & 3) * 32;     // 0,32,64,96
    const int warpN = (warp >> 2) * 96;    // 0,96
    const long long rowBase = (long long)blockIdx.x * 128;

    if (tid < 192)
        biasS[tid] = (tid < 128) ? ptb1[tid] : cfb1[tid - 128];

    float acc[2][12][4];
    #pragma unroll
    for (int mi = 0; mi < 2; ++mi)
        #pragma unroll
        for (int ni = 0; ni < 12; ++ni)
            #pragma unroll
            for (int r = 0; r < 4; ++r) acc[mi][ni][r] = 0.f;

    // per-thread load mapping
    const int rA = tid >> 1;                 // 0..127
    const int cA0 = (tid & 1) * 32;          // 0 or 32
    const int rB = tid >> 2;                 // 0..63 (k within chunk)
    const int cB0 = (tid & 3) * 48;          // 0,48,96,144

    for (int k0 = 0; k0 < KPAD; k0 += 64) {
        // ---- load A chunk 128x64 -> tf32 smem ----
        {
            const float4* src = reinterpret_cast<const float4*>(
                g_feats + (rowBase + rA) * KPAD + k0 + cA0);
            #pragma unroll
            for (int j = 0; j < 8; ++j) {
                float4 v = src[j];
                unsigned* d = As + rA * AS_STRIDE + cA0 + j * 4;
                d[0] = f2tf32(v.x); d[1] = f2tf32(v.y);
                d[2] = f2tf32(v.z); d[3] = f2tf32(v.w);
            }
        }
        // ---- load B chunk 64x192 (concat ptw1|cfw1, zero past K=584) ----
        {
            const int kr = k0 + rB;
            #pragma unroll
            for (int j = 0; j < 12; ++j) {
                const int col = cB0 + j * 4;
                float4 v;
                if (kr < FEAT) {
                    if (col < 128)
                        v = *reinterpret_cast<const float4*>(ptw1 + (long long)kr * 128 + col);
                    else
                        v = *reinterpret_cast<const float4*>(cfw1 + (long long)kr * 64 + col - 128);
                } else {
                    v = make_float4(0.f, 0.f, 0.f, 0.f);
                }
                unsigned* d = Bs + rB * BS_STRIDE + col;
                d[0] = f2tf32(v.x); d[1] = f2tf32(v.y);
                d[2] = f2tf32(v.z); d[3] = f2tf32(v.w);
            }
        }
        __syncthreads();

        // ---- compute: 8 k8-steps ----
        #pragma unroll
        for (int kk = 0; kk < 8; ++kk) {
            const int kb = kk * 8;
            unsigned a[2][4];
            #pragma unroll
            for (int mi = 0; mi < 2; ++mi) {
                const unsigned* ap = As + (warpM + mi * 16 + (lane >> 2)) * AS_STRIDE
                                        + kb + (lane & 3);
                a[mi][0] = ap[0];
                a[mi][1] = ap[8 * AS_STRIDE];
                a[mi][2] = ap[4];
                a[mi][3] = ap[8 * AS_STRIDE + 4];
            }
            #pragma unroll
            for (int ni = 0; ni < 12; ++ni) {
                const unsigned* bp = Bs + (kb + (lane & 3)) * BS_STRIDE
                                        + warpN + ni * 8 + (lane >> 2);
                unsigned b0 = bp[0];
                unsigned b1 = bp[4 * BS_STRIDE];
                #pragma unroll
                for (int mi = 0; mi < 2; ++mi) {
                    asm volatile(
                        "mma.sync.aligned.m16n8k8.row.col.f32.tf32.tf32.f32 "
                        "{%0,%1,%2,%3}, {%4,%5,%6,%7}, {%8,%9}, {%0,%1,%2,%3};\n"
                        : "+f"(acc[mi][ni][0]), "+f"(acc[mi][ni][1]),
                          "+f"(acc[mi][ni][2]), "+f"(acc[mi][ni][3])
                        : "r"(a[mi][0]), "r"(a[mi][1]), "r"(a[mi][2]), "r"(a[mi][3]),
                          "r"(b0), "r"(b1));
                }
            }
        }
        __syncthreads();
    }

    // ---- epilogue: bias + relu -> g_h1 (float2 stores) ----
    #pragma unroll
    for (int ni = 0; ni < 12; ++ni) {
        const int col = warpN + ni * 8 + 2 * (lane & 3);
        const float bx = biasS[col], by = biasS[col + 1];
        #pragma unroll
        for (int mi = 0; mi < 2; ++mi) {
            const long long r0 = rowBase + warpM + mi * 16 + (lane >> 2);
            float2 v0, v1;
            v0.x = fmaxf(acc[mi][ni][0] + bx, 0.f);
            v0.y = fmaxf(acc[mi][ni][1] + by, 0.f);
            v1.x = fmaxf(acc[mi][ni][2] + bx, 0.f);
            v1.y = fmaxf(acc[mi][ni][3] + by, 0.f);
            *reinterpret_cast<float2*>(g_h1 + r0 * 192 + col)       = v0;
            *reinterpret_cast<float2*>(g_h1 + (r0 + 8) * 192 + col) = v1;
        }
    }
}

// ============================================================================
// Kernel 3: heads. warp-per-sample. (unchanged)
// ============================================================================
__global__ void __launch_bounds__(256)
k3_heads(const float* __restrict__ ptw2, const float* __restrict__ ptb2,
         const float* __restrict__ ptw3, const float* __restrict__ ptb3,
         const float* __restrict__ cfw2, const float* __restrict__ cfb2,
         float* __restrict__ out)
{
    __shared__ float w2s[128 * 64];
    __shared__ float b2s[64], w3s[128], b3s[2], cw2s[64];
    __shared__ float rowS[8][256];

    const int tid = threadIdx.x;
    for (int i = tid; i < 128 * 64; i += 256) w2s[i] = ptw2[i];
    if (tid < 64)  b2s[tid]  = ptb2[tid];
    if (tid < 128) w3s[tid]  = ptw3[tid];
    if (tid < 2)   b3s[tid]  = ptb3[tid];
    if (tid < 64)  cw2s[tid] = cfw2[tid];
    const float cb2 = cfb2[0];
    __syncthreads();

    const int warp = tid >> 5, lane = tid & 31;
    const int s = blockIdx.x * 8 + warp;
    float* rw = rowS[warp];

    #pragma unroll
    for (int k = 0; k < 6; ++k) {
        int idx = lane + 32 * k;
        rw[idx] = g_h1[(long long)s * 192 + idx];
    }
    __syncwarp();

    const int j0 = lane, j1 = lane + 32;
    float t0 = b2s[j0], t1 = b2s[j1];
    #pragma unroll 4
    for (int k = 0; k < 128; ++k) {
        float f = rw[k];
        t0 = fmaf(f, w2s[k * 64 + j0], t0);
        t1 = fmaf(f, w2s[k * 64 + j1], t1);
    }
    rw[192 + j0] = fmaxf(t0, 0.f);
    rw[192 + j1] = fmaxf(t1, 0.f);
    __syncwarp();

    float res = 0.f;
    if (lane < 2) {
        float lg = b3s[lane];
        #pragma unroll 4
        for (int k = 0; k < 64; ++k) lg = fmaf(rw[192 + k], w3s[k * 2 + lane], lg);
        res = lg;
    } else if (lane == 2) {
        float cf = cb2;
        #pragma unroll 4
        for (int k = 0; k < 64; ++k) cf = fmaf(rw[128 + k], cw2s[k], cf);
        res = cf;
    }
    const float l0 = __shfl_sync(0xffffffffu, res, 0);
    const float l1 = __shfl_sync(0xffffffffu, res, 1);
    const float cz = __shfl_sync(0xffffffffu, res, 2);

    if (lane == 0) {
        float m = fmaxf(l0, l1);
        float e0 = expf(l0 - m), e1 = expf(l1 - m);
        float inv = 1.f / (e0 + e1);
        out[(long long)s * 3 + 0] = e0 * inv;
        out[(long long)s * 3 + 1] = e1 * inv;
        out[(long long)s * 3 + 2] = 1.f / (1.f + expf(-cz));
    }
}

// ============================================================================
extern "C" void kernel_launch(void* const* d_in, const int* in_sizes, int n_in,
                              void* d_out, int out_size)
{
    const float* board = (const float*)d_in[0];
    // d_in[1] = target_positions (int64) — mathematically unused
    const float* c1w  = (const float*)d_in[2];
    const float* c1b  = (const float*)d_in[3];
    const float* c2w  = (const float*)d_in[4];
    const float* c2b  = (const float*)d_in[5];
    const float* c3w  = (const float*)d_in[6];
    const float* c3b  = (const float*)d_in[7];
    const float* qp   = (const float*)d_in[8];
    const float* ptw1 = (const float*)d_in[9];
    const float* ptb1 = (const float*)d_in[10];
    const float* ptw2 = (const float*)d_in[11];
    const float* ptb2 = (const float*)d_in[12];
    const float* ptw3 = (const float*)d_in[13];
    const float* ptb3 = (const float*)d_in[14];
    const float* cfw1 = (const float*)d_in[15];
    const float* cfb1 = (const float*)d_in[16];
    const float* cfw2 = (const float*)d_in[17];
    const float* cfb2 = (const float*)d_in[18];

    cudaFuncSetAttribute(k1_conv, cudaFuncAttributeMaxDynamicSharedMemorySize,
                         SMEM1_FLOATS * (int)sizeof(float));
    cudaFuncSetAttribute(k2_gemm_tc, cudaFuncAttributeMaxDynamicSharedMemorySize,
                         SMEM2_FLOATS * (int)sizeof(float));

    k1_conv<<<B_TOTAL / K1_WARPS, K1_THREADS, SMEM1_FLOATS * sizeof(float)>>>(
        board, c1w, c1b, c2w, c2b, c3w, c3b, qp);

    k2_gemm_tc<<<B_TOTAL / 128, 256, SMEM2_FLOATS * sizeof(float)>>>(
        ptw1, ptb1, cfw1, cfb1);

    k3_heads<<<B_TOTAL / 8, 256>>>(ptw2, ptb2, ptw3, ptb3, cfw2, cfb2,
                                   (float*)d_out);
}